// round 5
// baseline (speedup 1.0000x reference)
#include <cuda_runtime.h>

#define M   1024
#define MM  (M*M)
#define TI  32
#define TJ  32
#define PAD 33

// Scratch: per-i complex accumulators for diag(Q1), diag(Q2), diag(Q3), and theta.
__device__ float g_acc[3][2][M];   // [which Q][re/im][i]
__device__ float g_theta[2][M];

// ---------------------------------------------------------------------------
// k0: zero accumulators (6144 floats)
// ---------------------------------------------------------------------------
__global__ void k0_zero() {
    int t = blockIdx.x * blockDim.x + threadIdx.x;
    ((float*)g_acc)[t] = 0.0f;
}

// ---------------------------------------------------------------------------
// k1: diag(Q) reductions.
//   dQ1[i] = sum_j A1[i,j] * p[j] * C1[j,i]   (complex)
//   dQ2[i] = sum_j A2[i,j] * p[j] * C2[j,i]
//   dQ3[i] = sum_j A2[i,j] * p[j] * C3[j,i]   (A2 reused!)
// Tiling: block owns TI=32 i's; iterates jChunk j's in 32x32 smem tiles.
// A tiles loaded row-major (coalesced over j); C tiles loaded row-major
// (coalesced over i) which IS the transpose we need.
// ---------------------------------------------------------------------------
__global__ __launch_bounds__(256) void k1_diag(
    const float* __restrict__ A1, const float* __restrict__ C1,
    const float* __restrict__ A2, const float* __restrict__ C2,
    const float* __restrict__ C3, const float* __restrict__ P,
    int jChunk)
{
    __shared__ float sA1[2][TI][PAD];
    __shared__ float sC1[2][TJ][PAD];
    __shared__ float sA2[2][TI][PAD];
    __shared__ float sC2[2][TJ][PAD];
    __shared__ float sC3[2][TJ][PAD];
    __shared__ float sp[2][TJ];

    const int i0 = blockIdx.x * TI;
    const int j0 = blockIdx.y * jChunk;
    const int t  = threadIdx.x;       // 0..255
    const int ti = t & 31;            // i within tile
    const int g  = t >> 5;            // 0..7 (j group)

    const int row = t >> 3;           // 0..31 (loader row)
    const int c4  = (t & 7) * 4;      // 0,4,...,28 (loader col, float4)

    float a1r = 0.f, a1i = 0.f, a2r = 0.f, a2i = 0.f, a3r = 0.f, a3i = 0.f;

    for (int jt = 0; jt < jChunk; jt += TJ) {
        const int j = j0 + jt;
        __syncthreads();   // previous tile's compute done before overwrite

        if (t < 64) sp[t >> 5][t & 31] = P[(t >> 5) * M + j + (t & 31)];

        #pragma unroll
        for (int c = 0; c < 2; c++) {
            float4 va1 = *(const float4*)&A1[c*MM + (i0 + row)*M + j  + c4];
            float4 va2 = *(const float4*)&A2[c*MM + (i0 + row)*M + j  + c4];
            float4 vc1 = *(const float4*)&C1[c*MM + (j  + row)*M + i0 + c4];
            float4 vc2 = *(const float4*)&C2[c*MM + (j  + row)*M + i0 + c4];
            float4 vc3 = *(const float4*)&C3[c*MM + (j  + row)*M + i0 + c4];
            sA1[c][row][c4+0]=va1.x; sA1[c][row][c4+1]=va1.y; sA1[c][row][c4+2]=va1.z; sA1[c][row][c4+3]=va1.w;
            sA2[c][row][c4+0]=va2.x; sA2[c][row][c4+1]=va2.y; sA2[c][row][c4+2]=va2.z; sA2[c][row][c4+3]=va2.w;
            sC1[c][row][c4+0]=vc1.x; sC1[c][row][c4+1]=vc1.y; sC1[c][row][c4+2]=vc1.z; sC1[c][row][c4+3]=vc1.w;
            sC2[c][row][c4+0]=vc2.x; sC2[c][row][c4+1]=vc2.y; sC2[c][row][c4+2]=vc2.z; sC2[c][row][c4+3]=vc2.w;
            sC3[c][row][c4+0]=vc3.x; sC3[c][row][c4+1]=vc3.y; sC3[c][row][c4+2]=vc3.z; sC3[c][row][c4+3]=vc3.w;
        }
        __syncthreads();

        #pragma unroll
        for (int k = 0; k < 4; k++) {
            const int tj = g * 4 + k;
            const float pr = sp[0][tj], pi = sp[1][tj];

            // ---- Q1: A1 * (p*C1) ----
            {
                float cr = sC1[0][tj][ti], ci = sC1[1][tj][ti];
                float xr = pr*cr - pi*ci, xi = pr*ci + pi*cr;
                float ar = sA1[0][ti][tj], ai = sA1[1][ti][tj];
                a1r += ar*xr - ai*xi;
                a1i += ar*xi + ai*xr;
            }
            const float Ar = sA2[0][ti][tj], Ai = sA2[1][ti][tj];
            // ---- Q2: A2 * (p*C2) ----
            {
                float cr = sC2[0][tj][ti], ci = sC2[1][tj][ti];
                float xr = pr*cr - pi*ci, xi = pr*ci + pi*cr;
                a2r += Ar*xr - Ai*xi;
                a2i += Ar*xi + Ai*xr;
            }
            // ---- Q3: A2 * (p*C3) ----
            {
                float cr = sC3[0][tj][ti], ci = sC3[1][tj][ti];
                float xr = pr*cr - pi*ci, xi = pr*ci + pi*cr;
                a3r += Ar*xr - Ai*xi;
                a3i += Ar*xi + Ai*xr;
            }
        }
    }

    // Cross-group reduction (8 partials per i). Reuse sA1 as scratch (2112 >= 1536 floats).
    __syncthreads();
    float* red = &sA1[0][0][0];
    red[t*6+0] = a1r; red[t*6+1] = a1i;
    red[t*6+2] = a2r; red[t*6+3] = a2i;
    red[t*6+4] = a3r; red[t*6+5] = a3i;
    __syncthreads();
    #pragma unroll
    for (int s = 4; s > 0; s >>= 1) {
        if (g < s) {
            #pragma unroll
            for (int q = 0; q < 6; q++)
                red[t*6+q] += red[(t + s*32)*6 + q];
        }
        __syncthreads();
    }
    if (g == 0) {
        const int i = i0 + ti;
        atomicAdd(&g_acc[0][0][i], red[ti*6+0]);
        atomicAdd(&g_acc[0][1][i], red[ti*6+1]);
        atomicAdd(&g_acc[1][0][i], red[ti*6+2]);
        atomicAdd(&g_acc[1][1][i], red[ti*6+3]);
        atomicAdd(&g_acc[2][0][i], red[ti*6+4]);
        atomicAdd(&g_acc[2][1][i], red[ti*6+5]);
    }
}

// ---------------------------------------------------------------------------
// k2: b[i] = a*(dA1*Th*dC1) - dQ1 + dB1
//          + b*(dA2*Th*dC2) - dQ2 + dB2
//          + b*(dA3*Th*dC3) - dQ3 + dB3 + param2 ; theta = b / |b|
// ---------------------------------------------------------------------------
__global__ void k2_theta(
    const float* __restrict__ Theta,
    const float* __restrict__ A1, const float* __restrict__ B1, const float* __restrict__ C1,
    const float* __restrict__ A2, const float* __restrict__ B2, const float* __restrict__ C2,
    const float* __restrict__ A3, const float* __restrict__ B3, const float* __restrict__ C3,
    const float* __restrict__ alpha, const float* __restrict__ belta,
    const float* __restrict__ param2)
{
    const int i = blockIdx.x * blockDim.x + threadIdx.x;
    if (i >= M) return;
    const int d = i * (M + 1);

    const float thr = Theta[d], thi = Theta[MM + d];
    const float al = alpha[0], be = belta[0];

    float tr_[3], ti_[3];
    const float* As[3] = {A1, A2, A3};
    const float* Cs[3] = {C1, C2, C3};
    #pragma unroll
    for (int m = 0; m < 3; m++) {
        float ar = As[m][d], ai = As[m][MM + d];
        float cr = Cs[m][d], ci = Cs[m][MM + d];
        float ur = thr*cr - thi*ci, ui = thr*ci + thi*cr;   // Th * C
        tr_[m] = ar*ur - ai*ui;                             // A * (Th*C)
        ti_[m] = ar*ui + ai*ur;
    }

    float br = al*tr_[0] - g_acc[0][0][i] + B1[d]
             + be*tr_[1] - g_acc[1][0][i] + B2[d]
             + be*tr_[2] - g_acc[2][0][i] + B3[d]
             + param2[i];
    float bi = al*ti_[0] - g_acc[0][1][i] + B1[MM + d]
             + be*ti_[1] - g_acc[1][1][i] + B2[MM + d]
             + be*ti_[2] - g_acc[2][1][i] + B3[MM + d]
             + param2[M + i];

    const float inv = rsqrtf(br*br + bi*bi);
    g_theta[0][i] = br * inv;
    g_theta[1][i] = bi * inv;
}

// ---------------------------------------------------------------------------
// k3: zero-fill output (float4 stores) and plant theta on the diagonals.
// ---------------------------------------------------------------------------
__global__ __launch_bounds__(256) void k3_out(float4* __restrict__ out, int nF4) {
    const int q = blockIdx.x * blockDim.x + threadIdx.x;
    if (q >= nF4) return;
    const int e     = q << 2;            // element index (max 2^21, fits int)
    const int plane = e >> 20;           // MM = 2^20
    const int pos   = e & (MM - 1);
    const int r     = pos >> 10;         // row
    const int c0    = pos & (M - 1);     // first column of this float4
    float4 v = make_float4(0.f, 0.f, 0.f, 0.f);
    const int dd = r - c0;
    if (dd >= 0 && dd < 4)
        ((float*)&v)[dd] = g_theta[plane][r];
    out[q] = v;
}

// ---------------------------------------------------------------------------
extern "C" void kernel_launch(void* const* d_in, const int* in_sizes, int n_in,
                              void* d_out, int out_size) {
    const float* Theta  = (const float*)d_in[0];
    const float* A1     = (const float*)d_in[1];
    const float* B1     = (const float*)d_in[2];
    const float* C1     = (const float*)d_in[3];
    const float* A2     = (const float*)d_in[4];
    const float* B2     = (const float*)d_in[5];
    const float* C2     = (const float*)d_in[6];
    const float* A3     = (const float*)d_in[7];
    const float* B3     = (const float*)d_in[8];
    const float* C3     = (const float*)d_in[9];
    const float* alpha  = (const float*)d_in[10];
    const float* belta  = (const float*)d_in[11];
    const float* param1 = (const float*)d_in[12];
    const float* param2 = (const float*)d_in[13];
    float* out = (float*)d_out;

    k0_zero<<<6, 1024>>>();

    const int GY = 16;                      // 512 blocks total
    dim3 g1(M / TI, GY);
    k1_diag<<<g1, 256>>>(A1, C1, A2, C2, C3, param1, M / GY);

    k2_theta<<<8, 128>>>(Theta, A1, B1, C1, A2, B2, C2, A3, B3, C3,
                         alpha, belta, param2);

    const int nF4 = out_size / 4;           // 524288
    k3_out<<<(nF4 + 255) / 256, 256>>>((float4*)out, nF4);
}